// round 16
// baseline (speedup 1.0000x reference)
#include <cuda_runtime.h>
#include <cuda_bf16.h>

#define B_ 64
#define T_ 1024
#define I_ 8
#define H_ 512
#define O_ 2
#define NOISE_STD_ 0.05f
#define ALPHA_ 0.2f

#define NT_    192          // w3=consumer(SMSP3), w2=epilogue(SMSP2), w0/w1/w4/w5=producers
#define RING_  16           // e-ring slots (32 KB)

#define SA_      8192.0f    // 2^13 scale for recurrence dots
#define SO_      2097152.0f // 2^21 scale for output dots
#define MAGIC_F  12582912.0f        // 2^23 + 2^22 round-to-int bias
// Single-warp REDUX of 32 biased floats: bias = 32*0x4B400000 mod 2^32 = 0x68000000.
// Re-bias: + (0x4B400000 - 0x68000000) = 0xE3400000.
#define REBIAS_I ((int)0xE3400000u)

typedef unsigned long long u64;

__device__ __forceinline__ float tanh_mufu(float x) {
    float r; asm("tanh.approx.f32 %0, %1;" : "=f"(r) : "f"(x)); return r;
}
__device__ __forceinline__ int redux_add_s32(int v) {
    int r; asm volatile("redux.sync.add.s32 %0, %1, 0xffffffff;" : "=r"(r) : "r"(v)); return r;
}
__device__ __forceinline__ float4 ldsv4(const float* p) {
    float4 v;
    unsigned a = (unsigned)__cvta_generic_to_shared(p);
    asm volatile("ld.volatile.shared.v4.f32 {%0,%1,%2,%3}, [%4];"
                 : "=f"(v.x), "=f"(v.y), "=f"(v.z), "=f"(v.w) : "r"(a));
    return v;
}
// volatile LDS.128 as two packed f32x2 words (low float in low 32 bits)
__device__ __forceinline__ void ldsu2(const float* p, u64& a, u64& b) {
    unsigned ad = (unsigned)__cvta_generic_to_shared(p);
    asm volatile("ld.volatile.shared.v2.u64 {%0,%1}, [%2];"
                 : "=l"(a), "=l"(b) : "r"(ad));
}
// L2-only 128-bit global load (epilogue must observe consumer's STGs)
__device__ __forceinline__ float4 ldgcg4(const float* p) {
    float4 v;
    asm volatile("ld.global.cg.v4.f32 {%0,%1,%2,%3}, [%4];"
                 : "=f"(v.x), "=f"(v.y), "=f"(v.z), "=f"(v.w) : "l"(p));
    return v;
}
// ---- packed f32x2 (PTX-only on sm_103a) ----
__device__ __forceinline__ u64 pack2(float x, float y) {
    u64 r; asm("mov.b64 %0, {%1, %2};" : "=l"(r) : "f"(x), "f"(y)); return r;
}
__device__ __forceinline__ void unpack2(u64 v, float& x, float& y) {
    asm("mov.b64 {%0, %1}, %2;" : "=f"(x), "=f"(y) : "l"(v));
}
__device__ __forceinline__ u64 fma2(u64 a, u64 b, u64 c) {
    u64 r; asm("fma.rn.f32x2 %0, %1, %2, %3;" : "=l"(r) : "l"(a), "l"(b), "l"(c)); return r;
}
__device__ __forceinline__ u64 mul2(u64 a, u64 b) {
    u64 r; asm("mul.rn.f32x2 %0, %1, %2;" : "=l"(r) : "l"(a), "l"(b)); return r;
}
__device__ __forceinline__ u64 add2(u64 a, u64 b) {
    u64 r; asm("add.rn.f32x2 %0, %1, %2;" : "=l"(r) : "l"(a), "l"(b)); return r;
}

__global__ __launch_bounds__(NT_, 1)
void lowrank_rnn_kernel(const float* __restrict__ input,   // (B,T,I)
                        const float* __restrict__ noise,   // (B,T,H)
                        const float* __restrict__ wi,      // (I,H)
                        const float* __restrict__ si,      // (I,)
                        const float* __restrict__ m,       // (H,R)
                        const float* __restrict__ n,       // (H,R)
                        const float* __restrict__ wo,      // (H,O)
                        const float* __restrict__ so,      // (O,)
                        const float* __restrict__ h0,      // (H,)
                        float* __restrict__ out,           // (B,T,O)
                        float* __restrict__ traj)          // (B,T,H)
{
    __shared__ float s_e[RING_][H_];       // e(t) = 0.05nz + alpha*proj + negmc
    __shared__ volatile int s_pcnt[4];     // producers: e ready through step pcnt-1
    __shared__ volatile int s_ccnt;        // consumer: steps finished (traj visible)

    const int b    = blockIdx.x;
    const int tid  = threadIdx.x;
    const int w    = tid >> 5;
    const int lane = tid & 31;

    const float cm = (ALPHA_ / (float)H_) / SA_;   // alpha/H and 1/Sa folded into m

    if (w != 3 && w != 2) {
        // =================== PRODUCER (warps 0,1,4,5) — identical to R15 ===========
        const int pw = (w < 2) ? w : w - 2;        // 0..3
        const int k0 = (pw * 32 + lane) * 4;

        float wif[I_][4];                          // wi * si * alpha
        #pragma unroll
        for (int i = 0; i < I_; ++i) {
            const float4 ww = *(const float4*)(wi + i * H_ + k0);
            const float  s  = si[i] * ALPHA_;
            wif[i][0] = ww.x * s; wif[i][1] = ww.y * s;
            wif[i][2] = ww.z * s; wif[i][3] = ww.w * s;
        }
        float negmc[4];                            // -MAGIC*(m0f+m1f), folded into e
        {
            const float4 mA = *(const float4*)(m + k0 * 2);
            const float4 mB = *(const float4*)(m + k0 * 2 + 4);
            negmc[0] = -MAGIC_F * (mA.x * cm + mA.y * cm);
            negmc[1] = -MAGIC_F * (mA.z * cm + mA.w * cm);
            negmc[2] = -MAGIC_F * (mB.x * cm + mB.y * cm);
            negmc[3] = -MAGIC_F * (mB.z * cm + mB.w * cm);
        }
        const float* nz_base = noise + (size_t)b * T_ * H_ + k0;
        const float* in_base = input + (size_t)b * T_ * I_;

        if (tid == 0) s_ccnt = 0;
        for (int s = 0; s < 8; ++s) {              // prologue: steps 0..7
            const float4 nz = *(const float4*)(nz_base + (size_t)s * H_);
            const float4 x0 = __ldg((const float4*)(in_base + s * I_));
            const float4 x1 = __ldg((const float4*)(in_base + s * I_ + 4));
            const float nza[4] = {nz.x, nz.y, nz.z, nz.w};
            float e[4];
            #pragma unroll
            for (int u = 0; u < 4; ++u) {
                float pp = fmaf(NOISE_STD_, nza[u], negmc[u]);
                pp = fmaf(x0.x, wif[0][u], pp);
                pp = fmaf(x0.y, wif[1][u], pp);
                pp = fmaf(x0.z, wif[2][u], pp);
                pp = fmaf(x0.w, wif[3][u], pp);
                pp = fmaf(x1.x, wif[4][u], pp);
                pp = fmaf(x1.y, wif[5][u], pp);
                pp = fmaf(x1.z, wif[6][u], pp);
                pp = fmaf(x1.w, wif[7][u], pp);
                e[u] = pp;
            }
            *(float4*)&s_e[s][k0] = make_float4(e[0], e[1], e[2], e[3]);
        }
        if (lane == 0) s_pcnt[pw] = 8;
        float4 rnz[4], rx0[4], rx1[4];
        #pragma unroll
        for (int j = 0; j < 4; ++j) {
            const int t = 8 + j;
            rnz[j] = *(const float4*)(nz_base + (size_t)t * H_);
            rx0[j] = __ldg((const float4*)(in_base + t * I_));
            rx1[j] = __ldg((const float4*)(in_base + t * I_ + 4));
        }
        __syncthreads();

        int ccached = 0;
        #pragma unroll 4
        for (int tp = 8; tp < T_; ++tp) {
            if (tp > ccached + 12) {
                ccached = s_ccnt;
                while (tp > ccached + 12) { __nanosleep(200); ccached = s_ccnt; }
            }
            const int j = tp & 3;
            const float4 nz = rnz[j];
            const float4 x0 = rx0[j];
            const float4 x1 = rx1[j];
            int tl = tp + 4; if (tl > T_ - 1) tl = T_ - 1;
            rnz[j] = *(const float4*)(nz_base + (size_t)tl * H_);
            rx0[j] = __ldg((const float4*)(in_base + tl * I_));
            rx1[j] = __ldg((const float4*)(in_base + tl * I_ + 4));

            const float nza[4] = {nz.x, nz.y, nz.z, nz.w};
            float e[4];
            #pragma unroll
            for (int u = 0; u < 4; ++u) {
                float pp = fmaf(NOISE_STD_, nza[u], negmc[u]);
                pp = fmaf(x0.x, wif[0][u], pp);
                pp = fmaf(x0.y, wif[1][u], pp);
                pp = fmaf(x0.z, wif[2][u], pp);
                pp = fmaf(x0.w, wif[3][u], pp);
                pp = fmaf(x1.x, wif[4][u], pp);
                pp = fmaf(x1.y, wif[5][u], pp);
                pp = fmaf(x1.z, wif[6][u], pp);
                pp = fmaf(x1.w, wif[7][u], pp);
                e[u] = pp;
            }
            *(float4*)&s_e[tp & (RING_ - 1)][k0] = make_float4(e[0], e[1], e[2], e[3]);

            if ((tp & 3) == 3) {
                __threadfence_block();
                if (lane == 0) s_pcnt[pw] = tp + 1;
            }
        }
    } else if (w == 2) {
        // ========= EPILOGUE (warp 2, SMSP2) — identical to R15 =========
        const float so0 = (so[0] / (float)H_) * SO_;
        const float so1 = (so[1] / (float)H_) * SO_;
        float wo0f[16], wo1f[16];
        #pragma unroll
        for (int jb = 0; jb < 4; ++jb) {
            const int k0 = jb * 128 + lane * 4;
            const float4 wA = *(const float4*)(wo + k0 * 2);
            const float4 wB = *(const float4*)(wo + k0 * 2 + 4);
            const int q = jb * 4;
            wo0f[q+0]=wA.x*so0; wo1f[q+0]=wA.y*so1; wo0f[q+1]=wA.z*so0; wo1f[q+1]=wA.w*so1;
            wo0f[q+2]=wB.x*so0; wo1f[q+2]=wB.y*so1; wo0f[q+3]=wB.z*so0; wo1f[q+3]=wB.w*so1;
        }
        const float* traj_base = traj + (size_t)b * T_ * H_ + lane * 4;
        float*       out_base  = out  + (size_t)b * T_ * O_;
        __syncthreads();

        int ccached = 0;
        for (int tc = 0; tc < T_; tc += 4) {
            if (ccached < tc + 4) {
                ccached = s_ccnt;
                while (ccached < tc + 4) { __nanosleep(200); ccached = s_ccnt; }
            }
            float4 h4[4][4];
            #pragma unroll
            for (int s = 0; s < 4; ++s)
                #pragma unroll
                for (int jb = 0; jb < 4; ++jb)
                    h4[s][jb] = ldgcg4(traj_base + (size_t)(tc + s) * H_ + jb * 128);

            #pragma unroll
            for (int s = 0; s < 4; ++s) {
                const float hv[16] = {h4[s][0].x,h4[s][0].y,h4[s][0].z,h4[s][0].w,
                                      h4[s][1].x,h4[s][1].y,h4[s][1].z,h4[s][1].w,
                                      h4[s][2].x,h4[s][2].y,h4[s][2].z,h4[s][2].w,
                                      h4[s][3].x,h4[s][3].y,h4[s][3].z,h4[s][3].w};
                float o0A = 0.f, o0B = 0.f, o1A = 0.f, o1B = 0.f;
                #pragma unroll
                for (int q = 0; q < 8; ++q) {
                    const float rA = tanh_mufu(hv[q]);
                    const float rB = tanh_mufu(hv[q + 8]);
                    o0A = fmaf(rA, wo0f[q], o0A);   o0B = fmaf(rB, wo0f[q+8], o0B);
                    o1A = fmaf(rA, wo1f[q], o1A);   o1B = fmaf(rB, wo1f[q+8], o1B);
                }
                const int U0 = redux_add_s32(__float2int_rn(o0A + o0B));
                const int U1 = redux_add_s32(__float2int_rn(o1A + o1B));
                if (lane == 0) {
                    const float o0 = (float)U0 * (1.0f / SO_);
                    const float o1 = (float)U1 * (1.0f / SO_);
                    *(float2*)(out_base + (size_t)(tc + s) * O_) = make_float2(o0, o1);
                }
            }
        }
    } else {
        // ====== CONSUMER (warp 3, SMSP3) — f32x2-packed recurrence ======
        // pair p = jb*2 + half covers units (k0, k0+1) with k0 = jb*128 + lane*4 (+2)
        u64 m0f2[8], m1f2[8], n0f2[8], n1f2[8], h2[8];
        #pragma unroll
        for (int jb = 0; jb < 4; ++jb) {
            const int k0 = jb * 128 + lane * 4;
            const float4 mA = *(const float4*)(m + k0 * 2);      // m[k0][0..1], m[k0+1][0..1]
            const float4 mB = *(const float4*)(m + k0 * 2 + 4);
            const float4 nA = *(const float4*)(n + k0 * 2);
            const float4 nB = *(const float4*)(n + k0 * 2 + 4);
            const float4 hh = *(const float4*)(h0 + k0);
            const int p = jb * 2;
            m0f2[p]   = pack2(mA.x * cm,  mA.z * cm);
            m1f2[p]   = pack2(mA.y * cm,  mA.w * cm);
            m0f2[p+1] = pack2(mB.x * cm,  mB.z * cm);
            m1f2[p+1] = pack2(mB.y * cm,  mB.w * cm);
            n0f2[p]   = pack2(nA.x * SA_, nA.z * SA_);
            n1f2[p]   = pack2(nA.y * SA_, nA.w * SA_);
            n0f2[p+1] = pack2(nB.x * SA_, nB.z * SA_);
            n1f2[p+1] = pack2(nB.y * SA_, nB.w * SA_);
            h2[p]     = pack2(hh.x, hh.y);
            h2[p+1]   = pack2(hh.z, hh.w);
        }
        const u64 C08 = pack2(1.0f - ALPHA_, 1.0f - ALPHA_);
        float* traj_base = traj + (size_t)b * T_ * H_ + lane * 4;

        // a(0): tanh + packed dots + magic REDUX
        float A0b, A1b;
        {
            u64 acc0 = 0, acc1 = 0;
            #pragma unroll
            for (int p = 0; p < 8; ++p) {
                float xl, xh; unpack2(h2[p], xl, xh);
                const u64 r2 = pack2(tanh_mufu(xl), tanh_mufu(xh));
                if (p == 0) { acc0 = mul2(r2, n0f2[p]); acc1 = mul2(r2, n1f2[p]); }
                else        { acc0 = fma2(r2, n0f2[p], acc0); acc1 = fma2(r2, n1f2[p], acc1); }
            }
            float a0l, a0h, a1l, a1h;
            unpack2(acc0, a0l, a0h); unpack2(acc1, a1l, a1h);
            A0b = __int_as_float(redux_add_s32(__float_as_int((a0l + a0h) + MAGIC_F)) + REBIAS_I);
            A1b = __int_as_float(redux_add_s32(__float_as_int((a1l + a1h) + MAGIC_F)) + REBIAS_I);
        }
        __syncthreads();

        u64 e2[8];
        #pragma unroll
        for (int jb = 0; jb < 4; ++jb)
            ldsu2(&s_e[0][jb * 128 + lane * 4], e2[jb * 2], e2[jb * 2 + 1]);
        int avail = 8;

        #pragma unroll 2
        for (int t = 0; t < T_; ++t) {
            const u64 A02 = pack2(A0b, A0b);
            const u64 A12 = pack2(A1b, A1b);

            // h(t+1) = 0.8h + e + A0*m0 + A1*m1  (packed, bias via negmc in e)
            #pragma unroll
            for (int p = 0; p < 8; ++p) {
                u64 hb = fma2(C08, h2[p], e2[p]);
                u64 hx = fma2(A02, m0f2[p], hb);
                h2[p]  = fma2(A12, m1f2[p], hx);
            }
            // traj[t] = h(t+1): 4x STG.128 (bit-identical layout)
            #pragma unroll
            for (int jb = 0; jb < 4; ++jb) {
                ulonglong2 st;
                st.x = h2[jb * 2]; st.y = h2[jb * 2 + 1];
                *(ulonglong2*)(traj_base + (size_t)t * H_ + jb * 128) = st;
            }
            // tanh + packed a-dots (2 chains)
            u64 accA0 = 0, accB0 = 0, accA1 = 0, accB1 = 0;
            #pragma unroll
            for (int p = 0; p < 4; ++p) {
                float xl, xh; unpack2(h2[p], xl, xh);
                const u64 r2 = pack2(tanh_mufu(xl), tanh_mufu(xh));
                float yl, yh; unpack2(h2[p + 4], yl, yh);
                const u64 s2 = pack2(tanh_mufu(yl), tanh_mufu(yh));
                if (p == 0) {
                    accA0 = mul2(r2, n0f2[0]);  accA1 = mul2(r2, n1f2[0]);
                    accB0 = mul2(s2, n0f2[4]);  accB1 = mul2(s2, n1f2[4]);
                } else {
                    accA0 = fma2(r2, n0f2[p], accA0);      accA1 = fma2(r2, n1f2[p], accA1);
                    accB0 = fma2(s2, n0f2[p + 4], accB0);  accB1 = fma2(s2, n1f2[p + 4], accB1);
                }
            }
            const u64 t0 = add2(accA0, accB0);
            const u64 t1 = add2(accA1, accB1);
            float a0l, a0h, a1l, a1h;
            unpack2(t0, a0l, a0h); unpack2(t1, a1l, a1h);
            const int W0 = redux_add_s32(__float_as_int((a0l + a0h) + MAGIC_F));
            const int W1 = redux_add_s32(__float_as_int((a1l + a1h) + MAGIC_F));

            // e(t+1) prefetch while REDUX is in flight
            int tn = t + 1; if (tn > T_ - 1) tn = T_ - 1;
            if (avail < tn + 1) {
                do {
                    avail = min(min(s_pcnt[0], s_pcnt[1]), min(s_pcnt[2], s_pcnt[3]));
                } while (avail < tn + 1);
            }
            {
                const int slot = tn & (RING_ - 1);
                #pragma unroll
                for (int jb = 0; jb < 4; ++jb)
                    ldsu2(&s_e[slot][jb * 128 + lane * 4], e2[jb * 2], e2[jb * 2 + 1]);
            }
            A0b = __int_as_float(W0 + REBIAS_I);
            A1b = __int_as_float(W1 + REBIAS_I);

            if ((t & 3) == 3) {                // orders traj STGs, then publish
                __syncwarp();
                __threadfence_block();
                if (lane == 0) s_ccnt = t + 1;
            }
        }
    }
}

extern "C" void kernel_launch(void* const* d_in, const int* in_sizes, int n_in,
                              void* d_out, int out_size) {
    const float* input = (const float*)d_in[0];
    const float* noise = (const float*)d_in[1];
    const float* wi    = (const float*)d_in[2];
    const float* si    = (const float*)d_in[3];
    const float* m     = (const float*)d_in[4];
    const float* n     = (const float*)d_in[5];
    const float* wo    = (const float*)d_in[6];
    const float* so    = (const float*)d_in[7];
    const float* h0    = (const float*)d_in[8];

    float* out  = (float*)d_out;                         // (B,T,O) first
    float* traj = (float*)d_out + (size_t)B_ * T_ * O_;  // then (B,T,H)

    lowrank_rnn_kernel<<<B_, NT_>>>(input, noise, wi, si, m, n, wo, so, h0,
                                    out, traj);
}